// round 9
// baseline (speedup 1.0000x reference)
#include <cuda_runtime.h>

#define SS 100
#define BB 32
#define EW 431080

typedef unsigned long long ull;

__device__ __align__(16) float g_mu[EW];
__device__ __align__(16) float g_sp[EW];
__device__ __align__(16) float g_musp[2 * EW];     // quads [mu0,mu1,sp0,sp1] per input pair
__device__ __align__(16) float g_w2[SS * 25600];   // [s][k][1280]: (p*25+r) in first 1250
__device__ __align__(16) float g_h1[SS * BB * 2880];   // [s][b][k][12][12]
__device__ __align__(16) float g_h2T[SS * 800 * BB];   // [s][i][b]
__device__ __align__(16) float g_h3P[SS * 500 * BB];   // [s][o/2][b][2]
__device__ __align__(16) float g_logT[SS * 10 * BB];   // [s][o][b]

// ---- packed f32x2 helpers -------------------------------------------------
__device__ __forceinline__ ull pk2(float lo, float hi) {
    ull r; asm("mov.b64 %0, {%1, %2};" : "=l"(r) : "f"(lo), "f"(hi)); return r;
}
__device__ __forceinline__ float2 upk2(ull v) {
    float2 f; asm("mov.b64 {%0, %1}, %2;" : "=f"(f.x), "=f"(f.y) : "l"(v)); return f;
}
__device__ __forceinline__ ull fma2(ull a, ull b, ull c) {
    ull d; asm("fma.rn.f32x2 %0, %1, %2, %3;" : "=l"(d) : "l"(a), "l"(b), "l"(c)); return d;
}

// ---------------------------------------------------------------------------
// K0: concat mu, softplus(rho) once; build musp quads
// ---------------------------------------------------------------------------
__global__ void k_params(const float* c1mw, const float* c1rw, const float* c1mb, const float* c1rb,
                         const float* c2mw, const float* c2rw, const float* c2mb, const float* c2rb,
                         const float* a1mw, const float* a1rw, const float* a1mb, const float* a1rb,
                         const float* a2mw, const float* a2rw, const float* a2mb, const float* a2rb) {
    int j = blockIdx.x * blockDim.x + threadIdx.x;
    if (j >= EW) return;
    float mu, rho;
    if      (j < 500)    { mu = c1mw[j];          rho = c1rw[j]; }
    else if (j < 520)    { mu = c1mb[j - 500];    rho = c1rb[j - 500]; }
    else if (j < 25520)  { mu = c2mw[j - 520];    rho = c2rw[j - 520]; }
    else if (j < 25570)  { mu = c2mb[j - 25520];  rho = c2rb[j - 25520]; }
    else if (j < 425570) { mu = a1mw[j - 25570];  rho = a1rw[j - 25570]; }
    else if (j < 426070) { mu = a1mb[j - 425570]; rho = a1rb[j - 425570]; }
    else if (j < 431070) { mu = a2mw[j - 426070]; rho = a2rw[j - 426070]; }
    else                 { mu = a2mb[j - 431070]; rho = a2rb[j - 431070]; }
    float sp = fmaxf(rho, 0.0f) + log1pf(expf(-fabsf(rho)));
    g_mu[j] = mu;
    g_sp[j] = sp;
    int base = (j >> 1) * 4 + (j & 1);
    g_musp[base] = mu;
    g_musp[base + 2] = sp;
}

// ---------------------------------------------------------------------------
// K0b: conv2 weights -> [s][k][1280] (p*25+r)
// ---------------------------------------------------------------------------
__global__ void k_w2(const float* __restrict__ e) {
    int s = blockIdx.y;
    int j = blockIdx.x * 256 + threadIdx.x;
    if (j >= 25000) return;
    int k = j / 1250, rem = j - k * 1250;
    int p = rem / 25, r = rem - p * 25;
    int je = 520 + p * 500 + k * 25 + r;
    g_w2[(size_t)s * 25600 + k * 1280 + rem] = g_mu[je] + g_sp[je] * e[(size_t)s * EW + je];
}

// ---------------------------------------------------------------------------
// K1: conv1 (1->20,5x5)+relu+pool -> g_h1. grid (100,16), 240 thr.
// Image-PAIR packed, zero packing movs.
// ---------------------------------------------------------------------------
__global__ void k_conv1(const float* __restrict__ x, const float* __restrict__ e) {
    __shared__ __align__(16) float sxP[1568];   // [pos][im0,im1]
    __shared__ __align__(16) float swD[1000];   // duplicated weights [p][25][2]
    __shared__ float sb1[20];
    int s = blockIdx.x, bp = blockIdx.y, t = threadIdx.x;
    int b0 = bp * 2;

    const float4* xa4 = (const float4*)(x + b0 * 784);
    const float4* xb4 = (const float4*)(x + (b0 + 1) * 784);
    if (t < 196) {
        float4 a = xa4[t], b = xb4[t];
        float4* dst = (float4*)(sxP + t * 8);
        dst[0] = make_float4(a.x, b.x, a.y, b.y);
        dst[1] = make_float4(a.z, b.z, a.w, b.w);
    }
    const float* es = e + (size_t)s * EW;
    if (t < 125) {
        float4 m = ((const float4*)g_mu)[t];
        float4 p4 = ((const float4*)g_sp)[t];
        float4 ev = ((const float4*)es)[t];
        float4 w;
        w.x = fmaf(p4.x, ev.x, m.x); w.y = fmaf(p4.y, ev.y, m.y);
        w.z = fmaf(p4.z, ev.z, m.z); w.w = fmaf(p4.w, ev.w, m.w);
        float4* dst = (float4*)(swD + t * 8);
        dst[0] = make_float4(w.x, w.x, w.y, w.y);
        dst[1] = make_float4(w.z, w.z, w.w, w.w);
    }
    if (t < 20) sb1[t] = g_mu[500 + t] + g_sp[500 + t] * es[500 + t];
    __syncthreads();

    int p = t / 12, Y = t % 12;
    float bias = sb1[p];
    ull pb = pk2(bias, bias);
    const ull* wq = (const ull*)swD + p * 25;
    float* out0 = g_h1 + (size_t)(s * BB + b0) * 2880 + p * 144 + Y * 12;
    float* out1 = out0 + 2880;

    #pragma unroll
    for (int xq = 0; xq < 4; xq++) {
        int cx0 = xq * 6;
        ull a0[6], a1[6];
        #pragma unroll
        for (int i = 0; i < 6; i++) { a0[i] = pb; a1[i] = pb; }
        #pragma unroll
        for (int rr = 0; rr < 6; rr++) {
            const ulonglong2* vp = (const ulonglong2*)(sxP + ((2 * Y + rr) * 28 + cx0) * 2);
            ull vd[10];
            #pragma unroll
            for (int i = 0; i < 5; i++) { ulonglong2 q = vp[i]; vd[2*i] = q.x; vd[2*i+1] = q.y; }
            if (rr < 5) {
                #pragma unroll
                for (int o = 0; o < 5; o++) {
                    ull wd = wq[rr * 5 + o];
                    #pragma unroll
                    for (int xo = 0; xo < 6; xo++) a0[xo] = fma2(wd, vd[xo + o], a0[xo]);
                }
            }
            if (rr >= 1) {
                #pragma unroll
                for (int o = 0; o < 5; o++) {
                    ull wd = wq[(rr - 1) * 5 + o];
                    #pragma unroll
                    for (int xo = 0; xo < 6; xo++) a1[xo] = fma2(wd, vd[xo + o], a1[xo]);
                }
            }
        }
        #pragma unroll
        for (int Xl = 0; Xl < 3; Xl++) {
            float2 u0 = upk2(a0[2 * Xl]), u1 = upk2(a0[2 * Xl + 1]);
            float2 v0 = upk2(a1[2 * Xl]), v1 = upk2(a1[2 * Xl + 1]);
            float m0 = fmaxf(fmaxf(u0.x, u1.x), fmaxf(v0.x, v1.x));
            float m1 = fmaxf(fmaxf(u0.y, u1.y), fmaxf(v0.y, v1.y));
            out0[3 * xq + Xl] = fmaxf(m0, 0.0f);
            out1[3 * xq + Xl] = fmaxf(m1, 0.0f);
        }
    }
}

// ---------------------------------------------------------------------------
// K2: conv2 (20->50,5x5)+relu+pool. grid (100, 8), 400 thr. Image-PAIR packed.
// k-CHUNKED weight staging: 5 channels per barrier.
// Dynamic smem: sinP[13440] | swc[12800] | sb2[64] = 105216 B
// ---------------------------------------------------------------------------
#define CONV2_SMEM ((13440 + 12800 + 64) * 4)
__global__ __launch_bounds__(400, 2) void k_conv2(const float* __restrict__ e) {
    extern __shared__ __align__(16) float dsm[];
    float* sinP = dsm;                       // 13440: [pr][k][row(28)][x][2]
    float* swc  = dsm + 13440;               // 12800: 5k x [p][25][2] dup (+pad)
    float* sb2  = dsm + 26240;               // 50
    int s = blockIdx.x, bq = blockIdx.y, t = threadIdx.x;

    {   // stage 4 images as 2 interleaved pairs, row pad 24->28
        const float* base = g_h1 + (size_t)(s * BB + bq * 4) * 2880;
        for (int u = t; u < 1440; u += 400) {
            int pr = u / 720, rem = u - pr * 720;
            int k = rem / 36, rem2 = rem - k * 36;
            int row = rem2 / 3, xq = rem2 - row * 3;
            const float* s0 = base + (2 * pr) * 2880 + k * 144 + row * 12 + xq * 4;
            float4 a = *(const float4*)s0;
            float4 b = *(const float4*)(s0 + 2880);
            float* dst = sinP + pr * 6720 + k * 336 + row * 28 + xq * 8;
            ((float4*)dst)[0] = make_float4(a.x, b.x, a.y, b.y);
            ((float4*)dst)[1] = make_float4(a.z, b.z, a.w, b.w);
        }
    }
    const float* es = e + (size_t)s * EW;
    if (t < 50) sb2[t] = g_mu[25520 + t] + g_sp[25520 + t] * es[25520 + t];

    int pr = t / 200, pq = t - pr * 200;
    int p = pq >> 2, Y = pq & 3;
    ull pacc0[8], pacc1[8];

    const float4* w4 = (const float4*)(g_w2 + (size_t)s * 25600);
    const float* sbase = sinP + pr * 6720;

    bool first = true;
    for (int kc = 0; kc < 4; kc++) {
        __syncthreads();
        // stage 5 k-channels of duplicated weights: 1600 float4 reads
        for (int u = t; u < 1600; u += 400) {
            float4 w = w4[kc * 1600 + u];
            int kl = u / 320, rem = u - kl * 320;
            float4* d = (float4*)(swc + kl * 2560) + 2 * rem;
            d[0] = make_float4(w.x, w.x, w.y, w.y);
            d[1] = make_float4(w.z, w.z, w.w, w.w);
        }
        __syncthreads();
        if (first) {
            first = false;
            ull pb = pk2(sb2[p], sb2[p]);
            #pragma unroll
            for (int i = 0; i < 8; i++) { pacc0[i] = pb; pacc1[i] = pb; }
        }
        #pragma unroll
        for (int kl = 0; kl < 5; kl++) {
            int k = kc * 5 + kl;
            const ull* wq = (const ull*)(swc + kl * 2560) + p * 25;
            const float* chanK = sbase + k * 336;
            #pragma unroll
            for (int rr = 0; rr < 6; rr++) {
                const ulonglong2* vp = (const ulonglong2*)(chanK + (2 * Y + rr) * 28);
                ull vd[12];
                #pragma unroll
                for (int i = 0; i < 6; i++) { ulonglong2 q = vp[i]; vd[2*i] = q.x; vd[2*i+1] = q.y; }
                if (rr < 5) {
                    #pragma unroll
                    for (int o = 0; o < 5; o++) {
                        ull wd = wq[rr * 5 + o];
                        #pragma unroll
                        for (int xo = 0; xo < 8; xo++) pacc0[xo] = fma2(wd, vd[xo + o], pacc0[xo]);
                    }
                }
                if (rr >= 1) {
                    #pragma unroll
                    for (int o = 0; o < 5; o++) {
                        ull wd = wq[(rr - 1) * 5 + o];
                        #pragma unroll
                        for (int xo = 0; xo < 8; xo++) pacc1[xo] = fma2(wd, vd[xo + o], pacc1[xo]);
                    }
                }
            }
        }
    }

    int b0 = bq * 4 + pr * 2;
    #pragma unroll
    for (int X = 0; X < 4; X++) {
        float2 u0 = upk2(pacc0[2 * X]), u1 = upk2(pacc0[2 * X + 1]);
        float2 v0 = upk2(pacc1[2 * X]), v1 = upk2(pacc1[2 * X + 1]);
        float m0 = fmaxf(fmaxf(u0.x, u1.x), fmaxf(v0.x, v1.x));
        float m1 = fmaxf(fmaxf(u0.y, u1.y), fmaxf(v0.y, v1.y));
        ull pv = pk2(fmaxf(m0, 0.0f), fmaxf(m1, 0.0f));
        *(ull*)&g_h2T[((size_t)s * 800 + p * 16 + Y * 4 + X) * 32 + b0] = pv;
    }
}

// ---------------------------------------------------------------------------
// K3: fc1 (800->500)+relu -> g_h3P. grid (50 sg, 10 og), 320 thr (10 warps).
// SG=2: 40KB smem, small acc footprint -> 500 blocks, deeper DRAM MLP.
// Exact tiling: warp w handles o = obase + j*10 + w, j<5.
// ---------------------------------------------------------------------------
#define FC1_SG 2
#define FC1_SMEM (FC1_SG * 80 * 64 * 4)
__global__ __launch_bounds__(320, 3) void k_fc1(const float* __restrict__ e) {
    extern __shared__ __align__(16) float sact[];   // [ss][m][b][2]
    int sg = blockIdx.x, og = blockIdx.y, t = threadIdx.x;
    int warp = t >> 5, lane = t & 31;
    int s0 = sg * FC1_SG;
    int obase = og * 50;
    const ull* sa = (const ull*)sact;

    ull acc[5][FC1_SG];
    #pragma unroll
    for (int j = 0; j < 5; j++)
        #pragma unroll
        for (int ss = 0; ss < FC1_SG; ss++) acc[j][ss] = 0ull;

    for (int c = 0; c < 5; c++) {
        __syncthreads();
        for (int u = t; u < FC1_SG * 80 * 8; u += 320) {
            int ss = u / 640, rem = u - ss * 640;
            int m = rem >> 3, b4 = (rem & 7) << 2;
            const float* src = g_h2T + (size_t)(s0 + ss) * 25600 + (size_t)(c * 160 + 2 * m) * 32 + b4;
            float4 r0 = *(const float4*)src;
            float4 r1 = *(const float4*)(src + 32);
            float* dst = sact + ((ss * 80 + m) * 32 + b4) * 2;
            ((float4*)dst)[0] = make_float4(r0.x, r1.x, r0.y, r1.y);
            ((float4*)dst)[1] = make_float4(r0.z, r1.z, r0.w, r1.w);
        }
        __syncthreads();

        #pragma unroll
        for (int j = 0; j < 5; j++) {
            int o = obase + j * 10 + warp;
            size_t ebase = 25570 + (size_t)o * 800 + c * 160;
            const ulonglong2* msq = ((const ulonglong2*)g_musp) + (ebase >> 1);
            const float* ep0 = e + (size_t)(s0 + 0) * EW + ebase;
            const float* ep1 = e + (size_t)(s0 + 1) * EW + ebase;
            const float* eps[FC1_SG] = {ep0, ep1};
            {   // head pair (local m=0)
                ulonglong2 qh = msq[0];
                #pragma unroll
                for (int ss = 0; ss < FC1_SG; ss++) {
                    ull ev = *(const ull*)(eps[ss]);
                    ull w = fma2(qh.y, ev, qh.x);
                    acc[j][ss] = fma2(w, sa[(ss * 80) * 32 + lane], acc[j][ss]);
                }
            }
            #pragma unroll 3
            for (int q = 0; q < 39; q++) {      // pairs 2q+1, 2q+2
                ulonglong2 q1 = msq[2 * q + 1];
                ulonglong2 q2 = msq[2 * q + 2];
                #pragma unroll
                for (int ss = 0; ss < FC1_SG; ss++) {
                    ulonglong2 ev = *(const ulonglong2*)(eps[ss] + 2 + 4 * q);
                    ull w1 = fma2(q1.y, ev.x, q1.x);
                    ull w2 = fma2(q2.y, ev.y, q2.x);
                    ull a = acc[j][ss];
                    a = fma2(w1, sa[(ss * 80 + 2 * q + 1) * 32 + lane], a);
                    a = fma2(w2, sa[(ss * 80 + 2 * q + 2) * 32 + lane], a);
                    acc[j][ss] = a;
                }
            }
            {   // tail pair (local m=79)
                ulonglong2 qt = msq[79];
                #pragma unroll
                for (int ss = 0; ss < FC1_SG; ss++) {
                    ull ev = *(const ull*)(eps[ss] + 158);
                    ull w = fma2(qt.y, ev, qt.x);
                    acc[j][ss] = fma2(w, sa[(ss * 80 + 79) * 32 + lane], acc[j][ss]);
                }
            }
        }
    }

    #pragma unroll
    for (int j = 0; j < 5; j++) {
        int o = obase + j * 10 + warp;
        #pragma unroll
        for (int ss = 0; ss < FC1_SG; ss++) {
            int s = s0 + ss;
            float2 u = upk2(acc[j][ss]);
            float bb = g_mu[425570 + o] + g_sp[425570 + o] * e[(size_t)s * EW + 425570 + o];
            g_h3P[(size_t)s * 16000 + (o >> 1) * 64 + lane * 2 + (o & 1)] =
                fmaxf(u.x + u.y + bb, 0.0f);
        }
    }
}

// ---------------------------------------------------------------------------
// K4: fc2 (500->10) -> g_logT. grid 100, 320 thr (warp = o).
// ---------------------------------------------------------------------------
__global__ void k_fc2(const float* __restrict__ e) {
    int s = blockIdx.x, t = threadIdx.x;
    int o = t >> 5, lane = t & 31;
    const float* es = e + (size_t)s * EW;
    const ulonglong2* ms = (const ulonglong2*)(g_musp + 2 * (size_t)(426070 + o * 500));
    const ull* e2 = (const ull*)(es + 426070 + o * 500);
    const ull* h2 = (const ull*)(g_h3P + (size_t)s * 16000);
    ull a = 0ull;
    #pragma unroll 5
    for (int q = 0; q < 250; q++) {
        ulonglong2 m = ms[q];
        ull w = fma2(m.y, e2[q], m.x);
        a = fma2(w, h2[q * 32 + lane], a);
    }
    float2 u = upk2(a);
    float bb = g_mu[431070 + o] + g_sp[431070 + o] * es[431070 + o];
    g_logT[((size_t)s * 10 + o) * 32 + lane] = u.x + u.y + bb;
}

// ---------------------------------------------------------------------------
// K5: log_softmax + mean over s -> out[b][10]. grid 32, 128 thr.
// ---------------------------------------------------------------------------
__global__ void k_final(float* __restrict__ out) {
    __shared__ float red[10 * 128];
    int b = blockIdx.x, t = threadIdx.x;
    float c[10];
    if (t < SS) {
        float v[10];
        float m = -1e30f;
        #pragma unroll
        for (int o = 0; o < 10; o++) {
            v[o] = g_logT[((size_t)t * 10 + o) * 32 + b];
            m = fmaxf(m, v[o]);
        }
        float se = 0.0f;
        #pragma unroll
        for (int o = 0; o < 10; o++) se += expf(v[o] - m);
        float lse = m + logf(se);
        #pragma unroll
        for (int o = 0; o < 10; o++) c[o] = v[o] - lse;
    } else {
        #pragma unroll
        for (int o = 0; o < 10; o++) c[o] = 0.0f;
    }
    #pragma unroll
    for (int o = 0; o < 10; o++) red[o * 128 + t] = c[o];
    __syncthreads();
    if (t < 10) {
        float sum = 0.0f;
        for (int i = 0; i < 128; i++) sum += red[t * 128 + i];
        out[b * 10 + t] = sum * (1.0f / SS);
    }
}

// ---------------------------------------------------------------------------
extern "C" void kernel_launch(void* const* d_in, const int* in_sizes, int n_in,
                              void* d_out, int out_size) {
    const float* x    = (const float*)d_in[0];
    const float* e    = (const float*)d_in[1];
    const float* c1mw = (const float*)d_in[2];
    const float* c1rw = (const float*)d_in[3];
    const float* c1mb = (const float*)d_in[4];
    const float* c1rb = (const float*)d_in[5];
    const float* c2mw = (const float*)d_in[6];
    const float* c2rw = (const float*)d_in[7];
    const float* c2mb = (const float*)d_in[8];
    const float* c2rb = (const float*)d_in[9];
    const float* a1mw = (const float*)d_in[10];
    const float* a1rw = (const float*)d_in[11];
    const float* a1mb = (const float*)d_in[12];
    const float* a1rb = (const float*)d_in[13];
    const float* a2mw = (const float*)d_in[14];
    const float* a2rw = (const float*)d_in[15];
    const float* a2mb = (const float*)d_in[16];
    const float* a2rb = (const float*)d_in[17];
    float* out = (float*)d_out;

    cudaFuncSetAttribute(k_conv2, cudaFuncAttributeMaxDynamicSharedMemorySize, CONV2_SMEM);
    cudaFuncSetAttribute(k_fc1,   cudaFuncAttributeMaxDynamicSharedMemorySize, FC1_SMEM);

    k_params<<<(EW + 255) / 256, 256>>>(c1mw, c1rw, c1mb, c1rb,
                                        c2mw, c2rw, c2mb, c2rb,
                                        a1mw, a1rw, a1mb, a1rb,
                                        a2mw, a2rw, a2mb, a2rb);
    k_w2<<<dim3(98, SS), 256>>>(e);
    k_conv1<<<dim3(SS, 16), 240>>>(x, e);
    k_conv2<<<dim3(SS, 8), 400, CONV2_SMEM>>>(e);
    k_fc1<<<dim3(50, 10), 320, FC1_SMEM>>>(e);
    k_fc2<<<SS, 320>>>(e);
    k_final<<<BB, 128>>>(out);
}

// round 12
// speedup vs baseline: 1.2688x; 1.2688x over previous
#include <cuda_runtime.h>

#define SS 100
#define BB 32
#define EW 431080

typedef unsigned long long ull;

__device__ __align__(16) float g_mu[EW];
__device__ __align__(16) float g_sp[EW];
__device__ __align__(16) float g_musp[2 * EW];     // quads [mu0,mu1,sp0,sp1] per input pair
__device__ __align__(16) float g_w2[SS * 25600];   // [s][k][1280]: (p*25+r) in first 1250
__device__ __align__(16) float g_h1[SS * BB * 2880];   // [s][b][k][12][12]
__device__ __align__(16) float g_h2T[SS * 800 * BB];   // [s][i][b]
__device__ __align__(16) float g_h3P[SS * 500 * BB];   // [s][o/2][b][2]
__device__ __align__(16) float g_logT[SS * 10 * BB];   // [s][o][b]

// ---- packed f32x2 helpers -------------------------------------------------
__device__ __forceinline__ ull pk2(float lo, float hi) {
    ull r; asm("mov.b64 %0, {%1, %2};" : "=l"(r) : "f"(lo), "f"(hi)); return r;
}
__device__ __forceinline__ float2 upk2(ull v) {
    float2 f; asm("mov.b64 {%0, %1}, %2;" : "=f"(f.x), "=f"(f.y) : "l"(v)); return f;
}
__device__ __forceinline__ ull fma2(ull a, ull b, ull c) {
    ull d; asm("fma.rn.f32x2 %0, %1, %2, %3;" : "=l"(d) : "l"(a), "l"(b), "l"(c)); return d;
}

// ---------------------------------------------------------------------------
// K0: concat mu, softplus(rho) once; build musp quads
// ---------------------------------------------------------------------------
__global__ void k_params(const float* c1mw, const float* c1rw, const float* c1mb, const float* c1rb,
                         const float* c2mw, const float* c2rw, const float* c2mb, const float* c2rb,
                         const float* a1mw, const float* a1rw, const float* a1mb, const float* a1rb,
                         const float* a2mw, const float* a2rw, const float* a2mb, const float* a2rb) {
    int j = blockIdx.x * blockDim.x + threadIdx.x;
    if (j >= EW) return;
    float mu, rho;
    if      (j < 500)    { mu = c1mw[j];          rho = c1rw[j]; }
    else if (j < 520)    { mu = c1mb[j - 500];    rho = c1rb[j - 500]; }
    else if (j < 25520)  { mu = c2mw[j - 520];    rho = c2rw[j - 520]; }
    else if (j < 25570)  { mu = c2mb[j - 25520];  rho = c2rb[j - 25520]; }
    else if (j < 425570) { mu = a1mw[j - 25570];  rho = a1rw[j - 25570]; }
    else if (j < 426070) { mu = a1mb[j - 425570]; rho = a1rb[j - 425570]; }
    else if (j < 431070) { mu = a2mw[j - 426070]; rho = a2rw[j - 426070]; }
    else                 { mu = a2mb[j - 431070]; rho = a2rb[j - 431070]; }
    float sp = fmaxf(rho, 0.0f) + log1pf(expf(-fabsf(rho)));
    g_mu[j] = mu;
    g_sp[j] = sp;
    int base = (j >> 1) * 4 + (j & 1);
    g_musp[base] = mu;
    g_musp[base + 2] = sp;
}

// ---------------------------------------------------------------------------
// K0b: conv2 weights -> [s][k][1280] (p*25+r)
// ---------------------------------------------------------------------------
__global__ void k_w2(const float* __restrict__ e) {
    int s = blockIdx.y;
    int j = blockIdx.x * 256 + threadIdx.x;
    if (j >= 25000) return;
    int k = j / 1250, rem = j - k * 1250;
    int p = rem / 25, r = rem - p * 25;
    int je = 520 + p * 500 + k * 25 + r;
    g_w2[(size_t)s * 25600 + k * 1280 + rem] = g_mu[je] + g_sp[je] * e[(size_t)s * EW + je];
}

// ---------------------------------------------------------------------------
// K1: conv1 (1->20,5x5)+relu+pool -> g_h1. grid (100,16), 240 thr.
// Image-PAIR packed, zero packing movs.
// ---------------------------------------------------------------------------
__global__ void k_conv1(const float* __restrict__ x, const float* __restrict__ e) {
    __shared__ __align__(16) float sxP[1568];   // [pos][im0,im1]
    __shared__ __align__(16) float swD[1000];   // duplicated weights [p][25][2]
    __shared__ float sb1[20];
    int s = blockIdx.x, bp = blockIdx.y, t = threadIdx.x;
    int b0 = bp * 2;

    const float4* xa4 = (const float4*)(x + b0 * 784);
    const float4* xb4 = (const float4*)(x + (b0 + 1) * 784);
    if (t < 196) {
        float4 a = xa4[t], b = xb4[t];
        float4* dst = (float4*)(sxP + t * 8);
        dst[0] = make_float4(a.x, b.x, a.y, b.y);
        dst[1] = make_float4(a.z, b.z, a.w, b.w);
    }
    const float* es = e + (size_t)s * EW;
    if (t < 125) {
        float4 m = ((const float4*)g_mu)[t];
        float4 p4 = ((const float4*)g_sp)[t];
        float4 ev = ((const float4*)es)[t];
        float4 w;
        w.x = fmaf(p4.x, ev.x, m.x); w.y = fmaf(p4.y, ev.y, m.y);
        w.z = fmaf(p4.z, ev.z, m.z); w.w = fmaf(p4.w, ev.w, m.w);
        float4* dst = (float4*)(swD + t * 8);
        dst[0] = make_float4(w.x, w.x, w.y, w.y);
        dst[1] = make_float4(w.z, w.z, w.w, w.w);
    }
    if (t < 20) sb1[t] = g_mu[500 + t] + g_sp[500 + t] * es[500 + t];
    __syncthreads();

    int p = t / 12, Y = t % 12;
    float bias = sb1[p];
    ull pb = pk2(bias, bias);
    const ull* wq = (const ull*)swD + p * 25;
    float* out0 = g_h1 + (size_t)(s * BB + b0) * 2880 + p * 144 + Y * 12;
    float* out1 = out0 + 2880;

    #pragma unroll
    for (int xq = 0; xq < 4; xq++) {
        int cx0 = xq * 6;
        ull a0[6], a1[6];
        #pragma unroll
        for (int i = 0; i < 6; i++) { a0[i] = pb; a1[i] = pb; }
        #pragma unroll
        for (int rr = 0; rr < 6; rr++) {
            const ulonglong2* vp = (const ulonglong2*)(sxP + ((2 * Y + rr) * 28 + cx0) * 2);
            ull vd[10];
            #pragma unroll
            for (int i = 0; i < 5; i++) { ulonglong2 q = vp[i]; vd[2*i] = q.x; vd[2*i+1] = q.y; }
            if (rr < 5) {
                #pragma unroll
                for (int o = 0; o < 5; o++) {
                    ull wd = wq[rr * 5 + o];
                    #pragma unroll
                    for (int xo = 0; xo < 6; xo++) a0[xo] = fma2(wd, vd[xo + o], a0[xo]);
                }
            }
            if (rr >= 1) {
                #pragma unroll
                for (int o = 0; o < 5; o++) {
                    ull wd = wq[(rr - 1) * 5 + o];
                    #pragma unroll
                    for (int xo = 0; xo < 6; xo++) a1[xo] = fma2(wd, vd[xo + o], a1[xo]);
                }
            }
        }
        #pragma unroll
        for (int Xl = 0; Xl < 3; Xl++) {
            float2 u0 = upk2(a0[2 * Xl]), u1 = upk2(a0[2 * Xl + 1]);
            float2 v0 = upk2(a1[2 * Xl]), v1 = upk2(a1[2 * Xl + 1]);
            float m0 = fmaxf(fmaxf(u0.x, u1.x), fmaxf(v0.x, v1.x));
            float m1 = fmaxf(fmaxf(u0.y, u1.y), fmaxf(v0.y, v1.y));
            out0[3 * xq + Xl] = fmaxf(m0, 0.0f);
            out1[3 * xq + Xl] = fmaxf(m1, 0.0f);
        }
    }
}

// ---------------------------------------------------------------------------
// K2: conv2 (20->50,5x5)+relu+pool. grid (100, 8), 400 thr. Image-PAIR packed.
// k-CHUNKED weight staging: 5 channels per barrier.
// Dynamic smem: sinP[13440] | swc[12800] | sb2[64] = 105216 B
// ---------------------------------------------------------------------------
#define CONV2_SMEM ((13440 + 12800 + 64) * 4)
__global__ __launch_bounds__(400, 2) void k_conv2(const float* __restrict__ e) {
    extern __shared__ __align__(16) float dsm[];
    float* sinP = dsm;                       // 13440: [pr][k][row(28)][x][2]
    float* swc  = dsm + 13440;               // 12800: 5k x [p][25][2] dup (+pad)
    float* sb2  = dsm + 26240;               // 50
    int s = blockIdx.x, bq = blockIdx.y, t = threadIdx.x;

    {   // stage 4 images as 2 interleaved pairs, row pad 24->28
        const float* base = g_h1 + (size_t)(s * BB + bq * 4) * 2880;
        for (int u = t; u < 1440; u += 400) {
            int pr = u / 720, rem = u - pr * 720;
            int k = rem / 36, rem2 = rem - k * 36;
            int row = rem2 / 3, xq = rem2 - row * 3;
            const float* s0 = base + (2 * pr) * 2880 + k * 144 + row * 12 + xq * 4;
            float4 a = *(const float4*)s0;
            float4 b = *(const float4*)(s0 + 2880);
            float* dst = sinP + pr * 6720 + k * 336 + row * 28 + xq * 8;
            ((float4*)dst)[0] = make_float4(a.x, b.x, a.y, b.y);
            ((float4*)dst)[1] = make_float4(a.z, b.z, a.w, b.w);
        }
    }
    const float* es = e + (size_t)s * EW;
    if (t < 50) sb2[t] = g_mu[25520 + t] + g_sp[25520 + t] * es[25520 + t];

    int pr = t / 200, pq = t - pr * 200;
    int p = pq >> 2, Y = pq & 3;
    ull pacc0[8], pacc1[8];

    const float4* w4 = (const float4*)(g_w2 + (size_t)s * 25600);
    const float* sbase = sinP + pr * 6720;

    bool first = true;
    for (int kc = 0; kc < 4; kc++) {
        __syncthreads();
        // stage 5 k-channels of duplicated weights: 1600 float4 reads
        for (int u = t; u < 1600; u += 400) {
            float4 w = w4[kc * 1600 + u];
            int kl = u / 320, rem = u - kl * 320;
            float4* d = (float4*)(swc + kl * 2560) + 2 * rem;
            d[0] = make_float4(w.x, w.x, w.y, w.y);
            d[1] = make_float4(w.z, w.z, w.w, w.w);
        }
        __syncthreads();
        if (first) {
            first = false;
            ull pb = pk2(sb2[p], sb2[p]);
            #pragma unroll
            for (int i = 0; i < 8; i++) { pacc0[i] = pb; pacc1[i] = pb; }
        }
        #pragma unroll
        for (int kl = 0; kl < 5; kl++) {
            int k = kc * 5 + kl;
            const ull* wq = (const ull*)(swc + kl * 2560) + p * 25;
            const float* chanK = sbase + k * 336;
            #pragma unroll
            for (int rr = 0; rr < 6; rr++) {
                const ulonglong2* vp = (const ulonglong2*)(chanK + (2 * Y + rr) * 28);
                ull vd[12];
                #pragma unroll
                for (int i = 0; i < 6; i++) { ulonglong2 q = vp[i]; vd[2*i] = q.x; vd[2*i+1] = q.y; }
                if (rr < 5) {
                    #pragma unroll
                    for (int o = 0; o < 5; o++) {
                        ull wd = wq[rr * 5 + o];
                        #pragma unroll
                        for (int xo = 0; xo < 8; xo++) pacc0[xo] = fma2(wd, vd[xo + o], pacc0[xo]);
                    }
                }
                if (rr >= 1) {
                    #pragma unroll
                    for (int o = 0; o < 5; o++) {
                        ull wd = wq[(rr - 1) * 5 + o];
                        #pragma unroll
                        for (int xo = 0; xo < 8; xo++) pacc1[xo] = fma2(wd, vd[xo + o], pacc1[xo]);
                    }
                }
            }
        }
    }

    int b0 = bq * 4 + pr * 2;
    #pragma unroll
    for (int X = 0; X < 4; X++) {
        float2 u0 = upk2(pacc0[2 * X]), u1 = upk2(pacc0[2 * X + 1]);
        float2 v0 = upk2(pacc1[2 * X]), v1 = upk2(pacc1[2 * X + 1]);
        float m0 = fmaxf(fmaxf(u0.x, u1.x), fmaxf(v0.x, v1.x));
        float m1 = fmaxf(fmaxf(u0.y, u1.y), fmaxf(v0.y, v1.y));
        ull pv = pk2(fmaxf(m0, 0.0f), fmaxf(m1, 0.0f));
        *(ull*)&g_h2T[((size_t)s * 800 + p * 16 + Y * 4 + X) * 32 + b0] = pv;
    }
}

// ---------------------------------------------------------------------------
// K3: fc1 (800->500)+relu -> g_h3P. grid (25 sg, 10 og), 320 thr (10 warps).
// SG=4 + q-OUTER / j-INNER: activation pairs hoisted to registers once per q
// and reused across all 5 o's -> act-LDS traffic / 5. Accumulation order per
// (o,s) identical to previous versions.
// ---------------------------------------------------------------------------
#define FC1_SG 4
#define FC1_SMEM (FC1_SG * 80 * 64 * 4)
__global__ __launch_bounds__(320, 2) void k_fc1(const float* __restrict__ e) {
    extern __shared__ __align__(16) float sact[];   // [ss][m][b][2]
    int sg = blockIdx.x, og = blockIdx.y, t = threadIdx.x;
    int warp = t >> 5, lane = t & 31;
    int s0 = sg * FC1_SG;
    int obase = og * 50;
    const ull* sa = (const ull*)sact;

    ull acc[5][FC1_SG];
    #pragma unroll
    for (int j = 0; j < 5; j++)
        #pragma unroll
        for (int ss = 0; ss < FC1_SG; ss++) acc[j][ss] = 0ull;

    for (int c = 0; c < 5; c++) {
        __syncthreads();
        for (int u = t; u < FC1_SG * 80 * 8; u += 320) {
            int ss = u / 640, rem = u - ss * 640;
            int m = rem >> 3, b4 = (rem & 7) << 2;
            const float* src = g_h2T + (size_t)(s0 + ss) * 25600 + (size_t)(c * 160 + 2 * m) * 32 + b4;
            float4 r0 = *(const float4*)src;
            float4 r1 = *(const float4*)(src + 32);
            float* dst = sact + ((ss * 80 + m) * 32 + b4) * 2;
            ((float4*)dst)[0] = make_float4(r0.x, r1.x, r0.y, r1.y);
            ((float4*)dst)[1] = make_float4(r0.z, r1.z, r0.w, r1.w);
        }
        __syncthreads();

        size_t cb = 25570 + (size_t)c * 160;

        {   // head: pair 0 of this chunk
            ull act0[FC1_SG];
            #pragma unroll
            for (int ss = 0; ss < FC1_SG; ss++) act0[ss] = sa[(ss * 80) * 32 + lane];
            #pragma unroll
            for (int j = 0; j < 5; j++) {
                size_t pb = cb + (size_t)(obase + j * 10 + warp) * 800;
                const ulonglong2* msq = (const ulonglong2*)g_musp + (pb >> 1);
                ulonglong2 qh = msq[0];
                #pragma unroll
                for (int ss = 0; ss < FC1_SG; ss++) {
                    ull ev = *(const ull*)(e + (size_t)(s0 + ss) * EW + pb);
                    acc[j][ss] = fma2(fma2(qh.y, ev, qh.x), act0[ss], acc[j][ss]);
                }
            }
        }

        #pragma unroll 2
        for (int q = 0; q < 39; q++) {       // pairs 2q+1, 2q+2
            ull a1r[FC1_SG], a2r[FC1_SG];
            #pragma unroll
            for (int ss = 0; ss < FC1_SG; ss++) {
                a1r[ss] = sa[(ss * 80 + 2 * q + 1) * 32 + lane];
                a2r[ss] = sa[(ss * 80 + 2 * q + 2) * 32 + lane];
            }
            #pragma unroll
            for (int j = 0; j < 5; j++) {
                size_t pb = cb + (size_t)(obase + j * 10 + warp) * 800;
                const ulonglong2* msq = (const ulonglong2*)g_musp + (pb >> 1);
                ulonglong2 q1 = msq[2 * q + 1];
                ulonglong2 q2 = msq[2 * q + 2];
                #pragma unroll
                for (int ss = 0; ss < FC1_SG; ss++) {
                    ulonglong2 ev = *(const ulonglong2*)(e + (size_t)(s0 + ss) * EW + pb + 2 + 4 * q);
                    ull a = acc[j][ss];
                    a = fma2(fma2(q1.y, ev.x, q1.x), a1r[ss], a);
                    a = fma2(fma2(q2.y, ev.y, q2.x), a2r[ss], a);
                    acc[j][ss] = a;
                }
            }
        }

        {   // tail: pair 79 (floats 158,159)
            ull actT[FC1_SG];
            #pragma unroll
            for (int ss = 0; ss < FC1_SG; ss++) actT[ss] = sa[(ss * 80 + 79) * 32 + lane];
            #pragma unroll
            for (int j = 0; j < 5; j++) {
                size_t pb = cb + (size_t)(obase + j * 10 + warp) * 800;
                const ulonglong2* msq = (const ulonglong2*)g_musp + (pb >> 1);
                ulonglong2 qt = msq[79];
                #pragma unroll
                for (int ss = 0; ss < FC1_SG; ss++) {
                    ull ev = *(const ull*)(e + (size_t)(s0 + ss) * EW + pb + 158);
                    acc[j][ss] = fma2(fma2(qt.y, ev, qt.x), actT[ss], acc[j][ss]);
                }
            }
        }
    }

    #pragma unroll
    for (int j = 0; j < 5; j++) {
        int o = obase + j * 10 + warp;
        #pragma unroll
        for (int ss = 0; ss < FC1_SG; ss++) {
            int s = s0 + ss;
            float2 u = upk2(acc[j][ss]);
            float bb = g_mu[425570 + o] + g_sp[425570 + o] * e[(size_t)s * EW + 425570 + o];
            g_h3P[(size_t)s * 16000 + (o >> 1) * 64 + lane * 2 + (o & 1)] =
                fmaxf(u.x + u.y + bb, 0.0f);
        }
    }
}

// ---------------------------------------------------------------------------
// K4: fc2 (500->10) -> g_logT. grid 100, 320 thr (warp = o).
// ---------------------------------------------------------------------------
__global__ void k_fc2(const float* __restrict__ e) {
    int s = blockIdx.x, t = threadIdx.x;
    int o = t >> 5, lane = t & 31;
    const float* es = e + (size_t)s * EW;
    const ulonglong2* ms = (const ulonglong2*)(g_musp + 2 * (size_t)(426070 + o * 500));
    const ull* e2 = (const ull*)(es + 426070 + o * 500);
    const ull* h2 = (const ull*)(g_h3P + (size_t)s * 16000);
    ull a = 0ull;
    #pragma unroll 5
    for (int q = 0; q < 250; q++) {
        ulonglong2 m = ms[q];
        ull w = fma2(m.y, e2[q], m.x);
        a = fma2(w, h2[q * 32 + lane], a);
    }
    float2 u = upk2(a);
    float bb = g_mu[431070 + o] + g_sp[431070 + o] * es[431070 + o];
    g_logT[((size_t)s * 10 + o) * 32 + lane] = u.x + u.y + bb;
}

// ---------------------------------------------------------------------------
// K5: log_softmax + mean over s -> out[b][10]. grid 32, 128 thr.
// ---------------------------------------------------------------------------
__global__ void k_final(float* __restrict__ out) {
    __shared__ float red[10 * 128];
    int b = blockIdx.x, t = threadIdx.x;
    float c[10];
    if (t < SS) {
        float v[10];
        float m = -1e30f;
        #pragma unroll
        for (int o = 0; o < 10; o++) {
            v[o] = g_logT[((size_t)t * 10 + o) * 32 + b];
            m = fmaxf(m, v[o]);
        }
        float se = 0.0f;
        #pragma unroll
        for (int o = 0; o < 10; o++) se += expf(v[o] - m);
        float lse = m + logf(se);
        #pragma unroll
        for (int o = 0; o < 10; o++) c[o] = v[o] - lse;
    } else {
        #pragma unroll
        for (int o = 0; o < 10; o++) c[o] = 0.0f;
    }
    #pragma unroll
    for (int o = 0; o < 10; o++) red[o * 128 + t] = c[o];
    __syncthreads();
    if (t < 10) {
        float sum = 0.0f;
        for (int i = 0; i < 128; i++) sum += red[t * 128 + i];
        out[b * 10 + t] = sum * (1.0f / SS);
    }
}

// ---------------------------------------------------------------------------
extern "C" void kernel_launch(void* const* d_in, const int* in_sizes, int n_in,
                              void* d_out, int out_size) {
    const float* x    = (const float*)d_in[0];
    const float* e    = (const float*)d_in[1];
    const float* c1mw = (const float*)d_in[2];
    const float* c1rw = (const float*)d_in[3];
    const float* c1mb = (const float*)d_in[4];
    const float* c1rb = (const float*)d_in[5];
    const float* c2mw = (const float*)d_in[6];
    const float* c2rw = (const float*)d_in[7];
    const float* c2mb = (const float*)d_in[8];
    const float* c2rb = (const float*)d_in[9];
    const float* a1mw = (const float*)d_in[10];
    const float* a1rw = (const float*)d_in[11];
    const float* a1mb = (const float*)d_in[12];
    const float* a1rb = (const float*)d_in[13];
    const float* a2mw = (const float*)d_in[14];
    const float* a2rw = (const float*)d_in[15];
    const float* a2mb = (const float*)d_in[16];
    const float* a2rb = (const float*)d_in[17];
    float* out = (float*)d_out;

    cudaFuncSetAttribute(k_conv2, cudaFuncAttributeMaxDynamicSharedMemorySize, CONV2_SMEM);
    cudaFuncSetAttribute(k_fc1,   cudaFuncAttributeMaxDynamicSharedMemorySize, FC1_SMEM);

    k_params<<<(EW + 255) / 256, 256>>>(c1mw, c1rw, c1mb, c1rb,
                                        c2mw, c2rw, c2mb, c2rb,
                                        a1mw, a1rw, a1mb, a1rb,
                                        a2mw, a2rw, a2mb, a2rb);
    k_w2<<<dim3(98, SS), 256>>>(e);
    k_conv1<<<dim3(SS, 16), 240>>>(x, e);
    k_conv2<<<dim3(SS, 8), 400, CONV2_SMEM>>>(e);
    k_fc1<<<dim3(25, 10), 320, FC1_SMEM>>>(e);
    k_fc2<<<SS, 320>>>(e);
    k_final<<<BB, 128>>>(out);
}